// round 1
// baseline (speedup 1.0000x reference)
#include <cuda_runtime.h>
#include <math.h>

#define NB   16
#define NC   256
#define NC8  32
#define HW   96
#define PIX  (HW*HW)     /* 9216 */
#define KK   11

// ---------------- scratch (static device globals; no allocation) -------------
__device__ float g_xT [NB*NC*PIX];    // x transposed [b,c,w,h]; reused as ohT later
__device__ float g_qw [NB*NC8*PIX];
__device__ float g_kw [NB*NC8*PIX];
__device__ float g_qhT[NB*NC8*PIX];
__device__ float g_khT[NB*NC8*PIX];
__device__ float g_vw [NB*NC*PIX];
__device__ float g_vhT[NB*NC*PIX];
__device__ float g_eh [NB*HW*PIX];    // [b,w,h,H]
__device__ float g_ew [NB*HW*PIX];    // [b,h,w,W]
__device__ float g_tmp[NB*NC*PIX];    // out_w in normal layout

// ---------------- tiled transpose: out[b,c,w,h] = in[b,c,h,w] ----------------
__global__ void transpose_kernel(const float* __restrict__ in, float* __restrict__ out)
{
    __shared__ float ts[32][33];
    const int tile = blockIdx.x;            // 0..8
    const int plane = blockIdx.y;           // b*C + c
    const int h0 = (tile % 3) * 32, w0 = (tile / 3) * 32;
    const float* ib = in + (size_t)plane * PIX;
    float* ob = out + (size_t)plane * PIX;
    const int col = threadIdx.x & 31, row = threadIdx.x >> 5;
    #pragma unroll
    for (int r = 0; r < 4; r++) {
        int h = row + r*8;
        ts[h][col] = ib[(h0 + h)*HW + w0 + col];
    }
    __syncthreads();
    #pragma unroll
    for (int r = 0; r < 4; r++) {
        int w = row + r*8;
        ob[(w0 + w)*HW + h0 + col] = ts[col][w];
    }
}

// ---------------- 1-D conv along last dim (1x11, zero pad 5) -----------------
// y[b,o,p,q] = bias[o] + sum_{c,t} W[o,c,t] * in[b,c,p,q+t-5]
// block: (p line, m-tile, b); 256 threads; thread tile RO x 6.
template<int BM, int RO>
__global__ void __launch_bounds__(256) conv1d_kernel(
    const float* __restrict__ in, const float* __restrict__ wt,
    const float* __restrict__ bias, float* __restrict__ out, int O)
{
    constexpr int BC = 8;
    constexpr int RQ = 6;
    constexpr int TQ = 16;
    __shared__ float in_s[BC][112];            // 106 used (halo zero-padded)
    __shared__ float w_s[BM][BC*KK + 1];       // stride 89 (conflict-free)
    const int tid = threadIdx.x;
    const int tq = tid % TQ, to = tid / TQ;
    const int p = blockIdx.x, b = blockIdx.z;
    const int o0 = blockIdx.y * BM;
    const float* inb = in + (size_t)b * NC * PIX + p * HW;

    float acc[RO][RQ];
    #pragma unroll
    for (int i = 0; i < RO; i++)
        #pragma unroll
        for (int j = 0; j < RQ; j++) acc[i][j] = 0.f;

    for (int c0 = 0; c0 < NC; c0 += BC) {
        __syncthreads();
        for (int idx = tid; idx < BC*106; idx += 256) {
            int c = idx / 106, pos = idx % 106;
            float v = 0.f;
            if (pos >= 5 && pos < 101) v = inb[(size_t)(c0 + c) * PIX + (pos - 5)];
            in_s[c][pos] = v;
        }
        {   // coalesced weight staging: each warp owns o-rows, lanes stream k
            int wid = tid >> 5, lane = tid & 31;
            for (int o = wid; o < BM; o += 8) {
                const float* wp = wt + (size_t)(o0 + o) * (NC*KK) + c0*KK;
                for (int k = lane; k < BC*KK; k += 32)
                    w_s[o][k] = wp[k];
            }
        }
        __syncthreads();
        #pragma unroll 2
        for (int c = 0; c < BC; c++) {
            float xv[16];                        // register-cached input window
            #pragma unroll
            for (int j = 0; j < 16; j++) xv[j] = in_s[c][tq*RQ + j];
            #pragma unroll
            for (int t = 0; t < KK; t++) {
                float wv[RO];
                #pragma unroll
                for (int i = 0; i < RO; i++) wv[i] = w_s[to*RO + i][c*KK + t];
                #pragma unroll
                for (int i = 0; i < RO; i++)
                    #pragma unroll
                    for (int j = 0; j < RQ; j++)
                        acc[i][j] = fmaf(wv[i], xv[j + t], acc[i][j]);
            }
        }
    }
    #pragma unroll
    for (int i = 0; i < RO; i++) {
        int o = o0 + to*RO + i;
        float bo = bias[o];
        float* ob = out + (size_t)(b * O + o) * PIX + p * HW + tq*RQ;
        #pragma unroll
        for (int j = 0; j < RQ; j++) ob[j] = acc[i][j] + bo;
    }
}

// ---------------- energy: E[i,j] = sum_c Q[c,i]*K[c,j] on one 96-line --------
// q,k: base (b*32)*PIX + l*HW, channel stride PIX. e: (b*96+l)*PIX + i*96 + j
template<bool DIAG>
__global__ void __launch_bounds__(256) energy_kernel(
    const float* __restrict__ q, const float* __restrict__ k, float* __restrict__ e)
{
    __shared__ float q_s[NC8][97], k_s[NC8][97];
    const int l = blockIdx.x, b = blockIdx.y, tid = threadIdx.x;
    const float* qb = q + (size_t)b * NC8 * PIX + l * HW;
    const float* kb = k + (size_t)b * NC8 * PIX + l * HW;
    for (int idx = tid; idx < NC8*HW; idx += 256) {
        int c = idx / HW, i = idx % HW;
        q_s[c][i] = qb[(size_t)c * PIX + i];
        k_s[c][i] = kb[(size_t)c * PIX + i];
    }
    __syncthreads();
    const int tj = tid % 16, ti = tid / 16;
    float acc[6][6];
    #pragma unroll
    for (int i = 0; i < 6; i++)
        #pragma unroll
        for (int j = 0; j < 6; j++) acc[i][j] = 0.f;
    for (int c = 0; c < NC8; c++) {
        float qa[6], ka[6];
        #pragma unroll
        for (int ii = 0; ii < 6; ii++) qa[ii] = q_s[c][ii*16 + ti];
        #pragma unroll
        for (int jj = 0; jj < 6; jj++) ka[jj] = k_s[c][jj*16 + tj];
        #pragma unroll
        for (int ii = 0; ii < 6; ii++)
            #pragma unroll
            for (int jj = 0; jj < 6; jj++)
                acc[ii][jj] = fmaf(qa[ii], ka[jj], acc[ii][jj]);
    }
    float* eb = e + (size_t)(b * HW + l) * PIX;
    #pragma unroll
    for (int ii = 0; ii < 6; ii++)
        #pragma unroll
        for (int jj = 0; jj < 6; jj++) {
            int i = ii*16 + ti, j = jj*16 + tj;
            eb[i*HW + j] = (DIAG && i == j) ? -INFINITY : acc[ii][jj];
        }
}

// ---------------- softmax over concat[e_h(96), e_w(96)], in place ------------
__global__ void softmax_kernel(float* __restrict__ eh, float* __restrict__ ew)
{
    const int gw = (blockIdx.x * blockDim.x + threadIdx.x) >> 5;   // pixel id
    const int lane = threadIdx.x & 31;
    const int b = gw / PIX, rem = gw % PIX, h = rem / HW, w = rem % HW;
    float* ph = eh + ((size_t)(b*HW + w) * HW + h) * HW;
    float* pw = ew + ((size_t)(b*HW + h) * HW + w) * HW;
    float v[6];
    v[0] = ph[lane]; v[1] = ph[lane+32]; v[2] = ph[lane+64];
    v[3] = pw[lane]; v[4] = pw[lane+32]; v[5] = pw[lane+64];
    float m = v[0];
    #pragma unroll
    for (int r = 1; r < 6; r++) m = fmaxf(m, v[r]);
    #pragma unroll
    for (int s = 16; s; s >>= 1) m = fmaxf(m, __shfl_xor_sync(0xffffffffu, m, s));
    float sum = 0.f;
    #pragma unroll
    for (int r = 0; r < 6; r++) { v[r] = expf(v[r] - m); sum += v[r]; }
    #pragma unroll
    for (int s = 16; s; s >>= 1) sum += __shfl_xor_sync(0xffffffffu, sum, s);
    float inv = 1.f / sum;
    ph[lane]    = v[0]*inv; ph[lane+32] = v[1]*inv; ph[lane+64] = v[2]*inv;
    pw[lane]    = v[3]*inv; pw[lane+32] = v[4]*inv; pw[lane+64] = v[5]*inv;
}

// ---------------- apply: O[c,q] = sum_k V[c,k]*A[q,k] on one line ------------
// v base: b*NC*PIX + l*HW (ch stride PIX); a: (b*96+l)*PIX; o: same form as v.
__global__ void __launch_bounds__(256) out_kernel(
    const float* __restrict__ v, const float* __restrict__ a, float* __restrict__ o)
{
    extern __shared__ float sh[];
    float (*A_s)[97] = reinterpret_cast<float(*)[97]>(sh);           // [96][97] A^T
    float (*V_s)[97] = reinterpret_cast<float(*)[97]>(sh + 96*97);   // [64][97]
    const int l = blockIdx.x, b = blockIdx.y, tid = threadIdx.x;
    const float* ab = a + (size_t)(b*HW + l) * PIX;
    for (int idx = tid; idx < PIX; idx += 256) {
        int qq = idx / HW, kk = idx % HW;
        A_s[kk][qq] = ab[idx];                 // transposed store, stride-97 safe
    }
    const float* vb = v + (size_t)b * NC * PIX + l * HW;
    float* ob = o + (size_t)b * NC * PIX + l * HW;
    const int tq = tid % 16, tc = tid / 16;
    for (int c0 = 0; c0 < NC; c0 += 64) {
        __syncthreads();
        for (int idx = tid; idx < 64*HW; idx += 256) {
            int cc = idx / HW, kk = idx % HW;
            V_s[cc][kk] = vb[(size_t)(c0 + cc) * PIX + kk];
        }
        __syncthreads();
        float acc[4][6];
        #pragma unroll
        for (int i = 0; i < 4; i++)
            #pragma unroll
            for (int j = 0; j < 6; j++) acc[i][j] = 0.f;
        #pragma unroll 4
        for (int kk = 0; kk < HW; kk++) {
            float va[4], aa[6];
            #pragma unroll
            for (int i = 0; i < 4; i++) va[i] = V_s[tc*4 + i][kk];
            #pragma unroll
            for (int j = 0; j < 6; j++) aa[j] = A_s[kk][j*16 + tq];
            #pragma unroll
            for (int i = 0; i < 4; i++)
                #pragma unroll
                for (int j = 0; j < 6; j++)
                    acc[i][j] = fmaf(va[i], aa[j], acc[i][j]);
        }
        #pragma unroll
        for (int i = 0; i < 4; i++)
            #pragma unroll
            for (int j = 0; j < 6; j++)
                ob[(size_t)(c0 + tc*4 + i) * PIX + j*16 + tq] = acc[i][j];
    }
}

// ---------------- final: out = gamma*(ohT^T + tmp) + x -----------------------
__global__ void fuse_kernel(const float* __restrict__ ohT, const float* __restrict__ tmp,
                            const float* __restrict__ x, const float* __restrict__ gamma,
                            float* __restrict__ out)
{
    __shared__ float ts[32][33];
    const int tile = blockIdx.x, plane = blockIdx.y;
    const int h0 = (tile % 3) * 32, w0 = (tile / 3) * 32;
    const size_t base = (size_t)plane * PIX;
    const int col = threadIdx.x & 31, row = threadIdx.x >> 5;
    #pragma unroll
    for (int r = 0; r < 4; r++) {
        int w = row + r*8;
        ts[w][col] = ohT[base + (w0 + w)*HW + h0 + col];   // ts[w'][h'] = ohT[w0+w'][h0+h']
    }
    __syncthreads();
    const float g = *gamma;
    #pragma unroll
    for (int r = 0; r < 4; r++) {
        int h = row + r*8;
        size_t idx = base + (h0 + h)*HW + w0 + col;
        out[idx] = g * (ts[col][h] + tmp[idx]) + x[idx];
    }
}

// ---------------- launch ------------------------------------------------------
extern "C" void kernel_launch(void* const* d_in, const int* in_sizes, int n_in,
                              void* d_out, int out_size)
{
    (void)in_sizes; (void)n_in; (void)out_size;
    const float* x     = (const float*)d_in[0];
    const float* wq_h  = (const float*)d_in[1];
    const float* bq_h  = (const float*)d_in[2];
    const float* wq_w  = (const float*)d_in[3];
    const float* bq_w  = (const float*)d_in[4];
    const float* wk_h  = (const float*)d_in[5];
    const float* bk_h  = (const float*)d_in[6];
    const float* wk_w  = (const float*)d_in[7];
    const float* bk_w  = (const float*)d_in[8];
    const float* wv_h  = (const float*)d_in[9];
    const float* bv_h  = (const float*)d_in[10];
    const float* wv_w  = (const float*)d_in[11];
    const float* bv_w  = (const float*)d_in[12];
    const float* gamma = (const float*)d_in[13];
    float* out = (float*)d_out;

    float *xT, *qw, *kw, *qhT, *khT, *vw, *vhT, *eh, *ew, *tmp;
    cudaGetSymbolAddress((void**)&xT,  g_xT);
    cudaGetSymbolAddress((void**)&qw,  g_qw);
    cudaGetSymbolAddress((void**)&kw,  g_kw);
    cudaGetSymbolAddress((void**)&qhT, g_qhT);
    cudaGetSymbolAddress((void**)&khT, g_khT);
    cudaGetSymbolAddress((void**)&vw,  g_vw);
    cudaGetSymbolAddress((void**)&vhT, g_vhT);
    cudaGetSymbolAddress((void**)&eh,  g_eh);
    cudaGetSymbolAddress((void**)&ew,  g_ew);
    cudaGetSymbolAddress((void**)&tmp, g_tmp);
    float* ohT = xT;   // reuse: xT dead after H-direction convs

    constexpr int OUT_SMEM = (96*97 + 64*97) * 4;   // 62080 B
    cudaFuncSetAttribute((const void*)out_kernel,
                         cudaFuncAttributeMaxDynamicSharedMemorySize, OUT_SMEM);

    // 1) transpose x
    transpose_kernel<<<dim3(9, NB*NC), 256>>>(x, xT);
    // 2) six 1-D convs (row direction; H-direction done in transposed space)
    conv1d_kernel<32,2><<<dim3(HW, 1, NB), 256>>>(x,  wq_w, bq_w, qw,  NC8);
    conv1d_kernel<32,2><<<dim3(HW, 1, NB), 256>>>(x,  wk_w, bk_w, kw,  NC8);
    conv1d_kernel<32,2><<<dim3(HW, 1, NB), 256>>>(xT, wq_h, bq_h, qhT, NC8);
    conv1d_kernel<32,2><<<dim3(HW, 1, NB), 256>>>(xT, wk_h, bk_h, khT, NC8);
    conv1d_kernel<64,4><<<dim3(HW, 4, NB), 256>>>(x,  wv_w, bv_w, vw,  NC);
    conv1d_kernel<64,4><<<dim3(HW, 4, NB), 256>>>(xT, wv_h, bv_h, vhT, NC);
    // 3) energies (+ diag mask on e_h)
    energy_kernel<true ><<<dim3(HW, NB), 256>>>(qhT, khT, eh);
    energy_kernel<false><<<dim3(HW, NB), 256>>>(qw,  kw,  ew);
    // 4) joint softmax over 192, in place -> attention maps
    softmax_kernel<<<(NB*PIX)/8, 256>>>(eh, ew);
    // 5) apply attention
    out_kernel<<<dim3(HW, NB), 256, OUT_SMEM>>>(vw,  ew, tmp);   // out_w -> tmp[b,c,h,w]
    out_kernel<<<dim3(HW, NB), 256, OUT_SMEM>>>(vhT, eh, ohT);   // out_h -> ohT[b,c,w,h]
    // 6) fuse: gamma*(out_h + out_w) + x
    fuse_kernel<<<dim3(9, NB*NC), 256>>>(ohT, tmp, x, gamma, out);
}

// round 3
// speedup vs baseline: 1.3702x; 1.3702x over previous
#include <cuda_runtime.h>
#include <math.h>
#include <stdint.h>

#define NB   16
#define NC   256
#define NC8  32
#define HW   96
#define PIX  (HW*HW)     /* 9216 */
#define KK   11

// ---------------- scratch (static device globals; no allocation) -------------
__device__ float g_xT [NB*NC*PIX];    // x transposed [b,c,w,h]; reused as ohT later
__device__ float g_qw [NB*NC8*PIX];
__device__ float g_kw [NB*NC8*PIX];
__device__ float g_qhT[NB*NC8*PIX];
__device__ float g_khT[NB*NC8*PIX];
__device__ float g_vw [NB*NC*PIX];
__device__ float g_vhT[NB*NC*PIX];
__device__ float g_eh [NB*HW*PIX];    // [b,w,h,H]
__device__ float g_ew [NB*HW*PIX];    // [b,h,w,W]
__device__ float g_tmp[NB*NC*PIX];    // out_w in normal layout

// ---------------- helpers ----------------------------------------------------
__device__ __forceinline__ uint32_t f2tf32(float x) {
    uint32_t u;
    asm("cvt.rna.tf32.f32 %0, %1;" : "=r"(u) : "f"(x));
    return u;
}

__device__ __forceinline__ void mma_tf32(float c[4],
    uint32_t a0, uint32_t a1, uint32_t a2, uint32_t a3,
    uint32_t b0, uint32_t b1)
{
    asm volatile(
        "mma.sync.aligned.m16n8k8.row.col.f32.tf32.tf32.f32 "
        "{%0,%1,%2,%3}, {%4,%5,%6,%7}, {%8,%9}, {%0,%1,%2,%3};"
        : "+f"(c[0]), "+f"(c[1]), "+f"(c[2]), "+f"(c[3])
        : "r"(a0), "r"(a1), "r"(a2), "r"(a3), "r"(b0), "r"(b1));
}

// ---------------- tiled transpose: out[b,c,w,h] = in[b,c,h,w] ----------------
__global__ void transpose_kernel(const float* __restrict__ in, float* __restrict__ out)
{
    __shared__ float ts[32][33];
    const int tile = blockIdx.x;            // 0..8
    const int plane = blockIdx.y;           // b*C + c
    const int h0 = (tile % 3) * 32, w0 = (tile / 3) * 32;
    const float* ib = in + (size_t)plane * PIX;
    float* ob = out + (size_t)plane * PIX;
    const int col = threadIdx.x & 31, row = threadIdx.x >> 5;
    #pragma unroll
    for (int r = 0; r < 4; r++) {
        int h = row + r*8;
        ts[h][col] = ib[(h0 + h)*HW + w0 + col];
    }
    __syncthreads();
    #pragma unroll
    for (int r = 0; r < 4; r++) {
        int w = row + r*8;
        ob[(w0 + w)*HW + h0 + col] = ts[col][w];
    }
}

// ---------------- fp32 1-D conv (q/k convs; precision-critical) --------------
template<int BM, int RO>
__global__ void __launch_bounds__(256) conv1d_kernel(
    const float* __restrict__ in, const float* __restrict__ wt,
    const float* __restrict__ bias, float* __restrict__ out, int O)
{
    constexpr int BC = 8;
    constexpr int RQ = 6;
    constexpr int TQ = 16;
    __shared__ float in_s[BC][112];            // 106 used (halo zero-padded)
    __shared__ float w_s[BM][BC*KK + 1];       // stride 89 (conflict-free)
    const int tid = threadIdx.x;
    const int tq = tid % TQ, to = tid / TQ;
    const int p = blockIdx.x, b = blockIdx.z;
    const int o0 = blockIdx.y * BM;
    const float* inb = in + (size_t)b * NC * PIX + p * HW;

    float acc[RO][RQ];
    #pragma unroll
    for (int i = 0; i < RO; i++)
        #pragma unroll
        for (int j = 0; j < RQ; j++) acc[i][j] = 0.f;

    for (int c0 = 0; c0 < NC; c0 += BC) {
        __syncthreads();
        for (int idx = tid; idx < BC*106; idx += 256) {
            int c = idx / 106, pos = idx % 106;
            float v = 0.f;
            if (pos >= 5 && pos < 101) v = inb[(size_t)(c0 + c) * PIX + (pos - 5)];
            in_s[c][pos] = v;
        }
        {
            int wid = tid >> 5, lane = tid & 31;
            for (int o = wid; o < BM; o += 8) {
                const float* wp = wt + (size_t)(o0 + o) * (NC*KK) + c0*KK;
                for (int k = lane; k < BC*KK; k += 32)
                    w_s[o][k] = wp[k];
            }
        }
        __syncthreads();
        #pragma unroll 2
        for (int c = 0; c < BC; c++) {
            float xv[16];
            #pragma unroll
            for (int j = 0; j < 16; j++) xv[j] = in_s[c][tq*RQ + j];
            #pragma unroll
            for (int t = 0; t < KK; t++) {
                float wv[RO];
                #pragma unroll
                for (int i = 0; i < RO; i++) wv[i] = w_s[to*RO + i][c*KK + t];
                #pragma unroll
                for (int i = 0; i < RO; i++)
                    #pragma unroll
                    for (int j = 0; j < RQ; j++)
                        acc[i][j] = fmaf(wv[i], xv[j + t], acc[i][j]);
            }
        }
    }
    #pragma unroll
    for (int i = 0; i < RO; i++) {
        int o = o0 + to*RO + i;
        float bo = bias[o];
        float* ob = out + (size_t)(b * O + o) * PIX + p * HW + tq*RQ;
        #pragma unroll
        for (int j = 0; j < RQ; j++) ob[j] = acc[i][j] + bo;
    }
}

// ---------------- tf32 MMA 1-D conv (v convs; error-tolerant) ----------------
// Block: BM=64 output channels x 2 lines (192 pixels). 8 warps:
// warp = wm (M-tile of 16 rows) x wl (line). Warp computes 16x96 via
// 12 m16n8 tiles, K = 8 channels per chunk, 11 taps as shifted B windows.
__global__ void __launch_bounds__(256) conv1d_tf32_kernel(
    const float* __restrict__ in, const float* __restrict__ wt,
    const float* __restrict__ bias, float* __restrict__ out, int O)
{
    constexpr int BM = 64;
    constexpr int BC = 8;
    constexpr int ISTR = 120;                 // bank-conflict-free B loads
    __shared__ uint32_t in_s[2][BC][ISTR];
    __shared__ uint32_t w_s[BM][BC*KK + 1];   // stride 89

    const int tid = threadIdx.x;
    const int warp = tid >> 5, lane = tid & 31;
    const int wm = warp & 3;                  // M-warp 0..3
    const int wl = warp >> 2;                 // line 0..1
    const int krow = lane & 3;                // k index within chunk (A col / B row)
    const int grp  = lane >> 2;               // A row / B col
    const int p0 = blockIdx.x * 2;
    const int b  = blockIdx.z;
    const int o0 = blockIdx.y * BM;
    const float* inb = in + (size_t)b * NC * PIX + p0 * HW;

    float acc[12][4];
    #pragma unroll
    for (int nt = 0; nt < 12; nt++)
        #pragma unroll
        for (int r = 0; r < 4; r++) acc[nt][r] = 0.f;

    for (int c0 = 0; c0 < NC; c0 += BC) {
        __syncthreads();
        // stage 2 input lines, tf32-rounded, zero halo (pos = q + 5)
        for (int idx = tid; idx < 2*BC*106; idx += 256) {
            int l = idx / (BC*106);
            int r = idx % (BC*106);
            int c = r / 106, pos = r % 106;
            float v = 0.f;
            if (pos >= 5 && pos < 101)
                v = inb[(size_t)(c0 + c) * PIX + l*HW + (pos - 5)];
            in_s[l][c][pos] = f2tf32(v);
        }
        // stage weights, tf32-rounded
        for (int o = warp; o < BM; o += 8) {
            const float* wp = wt + (size_t)(o0 + o) * (NC*KK) + c0*KK;
            for (int k = lane; k < BC*KK; k += 32)
                w_s[o][k] = f2tf32(wp[k]);
        }
        __syncthreads();

        #pragma unroll
        for (int t = 0; t < KK; t++) {
            // A fragment: W[o0 + wm*16 + grp(+8)][k = krow(+4)] at tap t
            uint32_t a0 = w_s[wm*16 + grp    ][ krow     *KK + t];
            uint32_t a1 = w_s[wm*16 + grp + 8][ krow     *KK + t];
            uint32_t a2 = w_s[wm*16 + grp    ][(krow + 4)*KK + t];
            uint32_t a3 = w_s[wm*16 + grp + 8][(krow + 4)*KK + t];
            #pragma unroll
            for (int nt = 0; nt < 12; nt++) {
                int pos = nt*8 + grp + t;     // shifted window
                uint32_t b0 = in_s[wl][krow    ][pos];
                uint32_t b1 = in_s[wl][krow + 4][pos];
                mma_tf32(acc[nt], a0, a1, a2, a3, b0, b1);
            }
        }
    }

    // epilogue: C fragment (row = grp(+8), col = 2*krow(+1)) + bias
    const int oLo = o0 + wm*16 + grp;
    const int oHi = oLo + 8;
    const float bLo = bias[oLo];
    const float bHi = bias[oHi];
    float* obLo = out + (size_t)(b * O + oLo) * PIX + (p0 + wl) * HW;
    float* obHi = out + (size_t)(b * O + oHi) * PIX + (p0 + wl) * HW;
    #pragma unroll
    for (int nt = 0; nt < 12; nt++) {
        int q = nt*8 + 2*krow;
        obLo[q]     = acc[nt][0] + bLo;
        obLo[q + 1] = acc[nt][1] + bLo;
        obHi[q]     = acc[nt][2] + bHi;
        obHi[q + 1] = acc[nt][3] + bHi;
    }
}

// ---------------- energy: E[i,j] = sum_c Q[c,i]*K[c,j] on one 96-line --------
template<bool DIAG>
__global__ void __launch_bounds__(256) energy_kernel(
    const float* __restrict__ q, const float* __restrict__ k, float* __restrict__ e)
{
    __shared__ float q_s[NC8][97], k_s[NC8][97];
    const int l = blockIdx.x, b = blockIdx.y, tid = threadIdx.x;
    const float* qb = q + (size_t)b * NC8 * PIX + l * HW;
    const float* kb = k + (size_t)b * NC8 * PIX + l * HW;
    for (int idx = tid; idx < NC8*HW; idx += 256) {
        int c = idx / HW, i = idx % HW;
        q_s[c][i] = qb[(size_t)c * PIX + i];
        k_s[c][i] = kb[(size_t)c * PIX + i];
    }
    __syncthreads();
    const int tj = tid % 16, ti = tid / 16;
    float acc[6][6];
    #pragma unroll
    for (int i = 0; i < 6; i++)
        #pragma unroll
        for (int j = 0; j < 6; j++) acc[i][j] = 0.f;
    for (int c = 0; c < NC8; c++) {
        float qa[6], ka[6];
        #pragma unroll
        for (int ii = 0; ii < 6; ii++) qa[ii] = q_s[c][ii*16 + ti];
        #pragma unroll
        for (int jj = 0; jj < 6; jj++) ka[jj] = k_s[c][jj*16 + tj];
        #pragma unroll
        for (int ii = 0; ii < 6; ii++)
            #pragma unroll
            for (int jj = 0; jj < 6; jj++)
                acc[ii][jj] = fmaf(qa[ii], ka[jj], acc[ii][jj]);
    }
    float* eb = e + (size_t)(b * HW + l) * PIX;
    #pragma unroll
    for (int ii = 0; ii < 6; ii++)
        #pragma unroll
        for (int jj = 0; jj < 6; jj++) {
            int i = ii*16 + ti, j = jj*16 + tj;
            eb[i*HW + j] = (DIAG && i == j) ? -INFINITY : acc[ii][jj];
        }
}

// ---------------- softmax over concat[e_h(96), e_w(96)], in place ------------
__global__ void softmax_kernel(float* __restrict__ eh, float* __restrict__ ew)
{
    const int gw = (blockIdx.x * blockDim.x + threadIdx.x) >> 5;   // pixel id
    const int lane = threadIdx.x & 31;
    const int b = gw / PIX, rem = gw % PIX, h = rem / HW, w = rem % HW;
    float* ph = eh + ((size_t)(b*HW + w) * HW + h) * HW;
    float* pw = ew + ((size_t)(b*HW + h) * HW + w) * HW;
    float v[6];
    v[0] = ph[lane]; v[1] = ph[lane+32]; v[2] = ph[lane+64];
    v[3] = pw[lane]; v[4] = pw[lane+32]; v[5] = pw[lane+64];
    float m = v[0];
    #pragma unroll
    for (int r = 1; r < 6; r++) m = fmaxf(m, v[r]);
    #pragma unroll
    for (int s = 16; s; s >>= 1) m = fmaxf(m, __shfl_xor_sync(0xffffffffu, m, s));
    float sum = 0.f;
    #pragma unroll
    for (int r = 0; r < 6; r++) { v[r] = expf(v[r] - m); sum += v[r]; }
    #pragma unroll
    for (int s = 16; s; s >>= 1) sum += __shfl_xor_sync(0xffffffffu, sum, s);
    float inv = 1.f / sum;
    ph[lane]    = v[0]*inv; ph[lane+32] = v[1]*inv; ph[lane+64] = v[2]*inv;
    pw[lane]    = v[3]*inv; pw[lane+32] = v[4]*inv; pw[lane+64] = v[5]*inv;
}

// ---------------- apply: O[c,q] = sum_k V[c,k]*A[q,k] on one line ------------
__global__ void __launch_bounds__(256) out_kernel(
    const float* __restrict__ v, const float* __restrict__ a, float* __restrict__ o)
{
    extern __shared__ float sh[];
    float (*A_s)[97] = reinterpret_cast<float(*)[97]>(sh);           // [96][97] A^T
    float (*V_s)[97] = reinterpret_cast<float(*)[97]>(sh + 96*97);   // [64][97]
    const int l = blockIdx.x, b = blockIdx.y, tid = threadIdx.x;
    const float* ab = a + (size_t)(b*HW + l) * PIX;
    for (int idx = tid; idx < PIX; idx += 256) {
        int qq = idx / HW, kk = idx % HW;
        A_s[kk][qq] = ab[idx];
    }
    const float* vb = v + (size_t)b * NC * PIX + l * HW;
    float* ob = o + (size_t)b * NC * PIX + l * HW;
    const int tq = tid % 16, tc = tid / 16;
    for (int c0 = 0; c0 < NC; c0 += 64) {
        __syncthreads();
        for (int idx = tid; idx < 64*HW; idx += 256) {
            int cc = idx / HW, kk = idx % HW;
            V_s[cc][kk] = vb[(size_t)(c0 + cc) * PIX + kk];
        }
        __syncthreads();
        float acc[4][6];
        #pragma unroll
        for (int i = 0; i < 4; i++)
            #pragma unroll
            for (int j = 0; j < 6; j++) acc[i][j] = 0.f;
        #pragma unroll 4
        for (int kk = 0; kk < HW; kk++) {
            float va[4], aa[6];
            #pragma unroll
            for (int i = 0; i < 4; i++) va[i] = V_s[tc*4 + i][kk];
            #pragma unroll
            for (int j = 0; j < 6; j++) aa[j] = A_s[kk][j*16 + tq];
            #pragma unroll
            for (int i = 0; i < 4; i++)
                #pragma unroll
                for (int j = 0; j < 6; j++)
                    acc[i][j] = fmaf(va[i], aa[j], acc[i][j]);
        }
        #pragma unroll
        for (int i = 0; i < 4; i++)
            #pragma unroll
            for (int j = 0; j < 6; j++)
                ob[(size_t)(c0 + tc*4 + i) * PIX + j*16 + tq] = acc[i][j];
    }
}

// ---------------- final: out = gamma*(ohT^T + tmp) + x -----------------------
__global__ void fuse_kernel(const float* __restrict__ ohT, const float* __restrict__ tmp,
                            const float* __restrict__ x, const float* __restrict__ gamma,
                            float* __restrict__ out)
{
    __shared__ float ts[32][33];
    const int tile = blockIdx.x, plane = blockIdx.y;
    const int h0 = (tile % 3) * 32, w0 = (tile / 3) * 32;
    const size_t base = (size_t)plane * PIX;
    const int col = threadIdx.x & 31, row = threadIdx.x >> 5;
    #pragma unroll
    for (int r = 0; r < 4; r++) {
        int w = row + r*8;
        ts[w][col] = ohT[base + (w0 + w)*HW + h0 + col];
    }
    __syncthreads();
    const float g = *gamma;
    #pragma unroll
    for (int r = 0; r < 4; r++) {
        int h = row + r*8;
        size_t idx = base + (h0 + h)*HW + w0 + col;
        out[idx] = g * (ts[col][h] + tmp[idx]) + x[idx];
    }
}

// ---------------- launch ------------------------------------------------------
extern "C" void kernel_launch(void* const* d_in, const int* in_sizes, int n_in,
                              void* d_out, int out_size)
{
    (void)in_sizes; (void)n_in; (void)out_size;
    const float* x     = (const float*)d_in[0];
    const float* wq_h  = (const float*)d_in[1];
    const float* bq_h  = (const float*)d_in[2];
    const float* wq_w  = (const float*)d_in[3];
    const float* bq_w  = (const float*)d_in[4];
    const float* wk_h  = (const float*)d_in[5];
    const float* bk_h  = (const float*)d_in[6];
    const float* wk_w  = (const float*)d_in[7];
    const float* bk_w  = (const float*)d_in[8];
    const float* wv_h  = (const float*)d_in[9];
    const float* bv_h  = (const float*)d_in[10];
    const float* wv_w  = (const float*)d_in[11];
    const float* bv_w  = (const float*)d_in[12];
    const float* gamma = (const float*)d_in[13];
    float* out = (float*)d_out;

    float *xT, *qw, *kw, *qhT, *khT, *vw, *vhT, *eh, *ew, *tmp;
    cudaGetSymbolAddress((void**)&xT,  g_xT);
    cudaGetSymbolAddress((void**)&qw,  g_qw);
    cudaGetSymbolAddress((void**)&kw,  g_kw);
    cudaGetSymbolAddress((void**)&qhT, g_qhT);
    cudaGetSymbolAddress((void**)&khT, g_khT);
    cudaGetSymbolAddress((void**)&vw,  g_vw);
    cudaGetSymbolAddress((void**)&vhT, g_vhT);
    cudaGetSymbolAddress((void**)&eh,  g_eh);
    cudaGetSymbolAddress((void**)&ew,  g_ew);
    cudaGetSymbolAddress((void**)&tmp, g_tmp);
    float* ohT = xT;   // reuse: xT dead after H-direction convs

    constexpr int OUT_SMEM = (96*97 + 64*97) * 4;   // 62080 B
    cudaFuncSetAttribute((const void*)out_kernel,
                         cudaFuncAttributeMaxDynamicSharedMemorySize, OUT_SMEM);

    // 1) transpose x
    transpose_kernel<<<dim3(9, NB*NC), 256>>>(x, xT);
    // 2) q/k convs: fp32 (precision-critical — logits amplify conv error)
    conv1d_kernel<32,2><<<dim3(HW, 1, NB), 256>>>(x,  wq_w, bq_w, qw,  NC8);
    conv1d_kernel<32,2><<<dim3(HW, 1, NB), 256>>>(x,  wk_w, bk_w, kw,  NC8);
    conv1d_kernel<32,2><<<dim3(HW, 1, NB), 256>>>(xT, wq_h, bq_h, qhT, NC8);
    conv1d_kernel<32,2><<<dim3(HW, 1, NB), 256>>>(xT, wk_h, bk_h, khT, NC8);
    //    v convs: tf32 tensor cores (error-tolerant, 75% of conv FLOPs)
    conv1d_tf32_kernel<<<dim3(HW/2, NC/64, NB), 256>>>(x,  wv_w, bv_w, vw,  NC);
    conv1d_tf32_kernel<<<dim3(HW/2, NC/64, NB), 256>>>(xT, wv_h, bv_h, vhT, NC);
    // 3) energies (+ diag mask on e_h)
    energy_kernel<true ><<<dim3(HW, NB), 256>>>(qhT, khT, eh);
    energy_kernel<false><<<dim3(HW, NB), 256>>>(qw,  kw,  ew);
    // 4) joint softmax over 192, in place -> attention maps
    softmax_kernel<<<(NB*PIX)/8, 256>>>(eh, ew);
    // 5) apply attention
    out_kernel<<<dim3(HW, NB), 256, OUT_SMEM>>>(vw,  ew, tmp);   // out_w -> tmp[b,c,h,w]
    out_kernel<<<dim3(HW, NB), 256, OUT_SMEM>>>(vhT, eh, ohT);   // out_h -> ohT[b,c,w,h]
    // 6) fuse: gamma*(out_h + out_w) + x
    fuse_kernel<<<dim3(9, NB*NC), 256>>>(ohT, tmp, x, gamma, out);
}